// round 16
// baseline (speedup 1.0000x reference)
#include <cuda_runtime.h>
#include <cuda_fp16.h>
#include <math.h>

#define BATCH   256
#define JN      10
#define ICAPS   1152
#define DN      16
#define JD      160          // JN*DN
#define BJD     (BATCH*JD)   // 40960
#define IT      32           // i per pass warp
#define NP      (ICAPS/IT)   // 36 partial slices
#define GW      4            // warps per pass CTA

// -------- scratch ------------------------------------------------------
// u_hat layout: [i][b][j][d] halves (32B per (i,b,j) entry; i outermost)
__device__ __align__(1024) __half g_uhat[(size_t)ICAPS * BATCH * JD]; // ~94.4MB
__device__ float g_acc[2 * BJD];                 // [0]=s0raw, [1]=s1
__device__ float g_part[(size_t)NP * BJD];       // ~5.9 MB

// -------- MUFU-free exp / reciprocal (FMA+ALU pipes) ---------------------
__device__ __forceinline__ float fexp(float a) {
    float t = a * 1.44269504f;
    float m = t + 12582912.0f;
    int  ki = __float_as_int(m) - 0x4B400000;
    float f = t - (m - 12582912.0f);
    float p =             9.61812910e-3f;
    p = fmaf(p, f, 5.55041087e-2f);
    p = fmaf(p, f, 2.40226507e-1f);
    p = fmaf(p, f, 6.93147181e-1f);
    p = fmaf(p, f, 1.0f);
    return __int_as_float(__float_as_int(p) + (ki << 23));
}
__device__ __forceinline__ float frcp(float x) {
    float r = __int_as_float(0x7EF311C3 - __float_as_int(x));
    r = r * fmaf(-x, r, 2.0f);
    r = r * fmaf(-x, r, 2.0f);
    return r;
}
__device__ __forceinline__ float dot4(float4 w, float4 v) {
    return fmaf(w.x, v.x, fmaf(w.y, v.y, fmaf(w.z, v.z, w.w * v.w)));
}

// -------- K1: u_hat = W @ x (fp16 [i][b][jd]), scalar FMA, occ-3 ---------
// grid (144, 4), 320 threads: i-tile 8, b-tile 64.
// t%80 = jd2 (j*8+dp), t/80 = seg (16 b each, 2 bt groups of 8).
__global__ __launch_bounds__(320, 3) void k_uhat(const float* __restrict__ x,
                                                 const float* __restrict__ W) {
    __shared__ __align__(16) float4 xs4[64 * 8 * 2];   // 16 KB: [b][ii][qe]
    const int i0 = blockIdx.x * 8;
    const int b0 = blockIdx.y * 64;
    const int t  = threadIdx.x;

    const float4* xg = (const float4*)x;   // [256][1152][8] -> 2304 f4 per b
    for (int f = t; f < 1024; f += 320) {
        int b = f >> 4, q = f & 15;        // q = ii*2 + qe, ii<8
        xs4[b * 16 + q] = xg[(size_t)(b0 + b) * 2304 + (size_t)i0 * 2 + q];
    }
    __syncthreads();

    const int jd2 = t % 80;                // j*8 + dp  (d0 = 2*dp)
    const int seg = t / 80;
    const int j   = jd2 >> 3, dp = jd2 & 7;
    const float4* Wg = (const float4*)W + (size_t)j * 36864 + dp * 4;
    __half2* uh2 = (__half2*)g_uhat;

    for (int bt = 0; bt < 2; bt++) {
        const int bbase = seg * 16 + bt * 8;
        float acc0[8] = {0,0,0,0,0,0,0,0};
        float acc1[8] = {0,0,0,0,0,0,0,0};
        #pragma unroll
        for (int ii = 0; ii < 8; ii++) {
            const int i = i0 + ii;
            const float4 w00 = Wg[(size_t)i * 32];
            const float4 w01 = Wg[(size_t)i * 32 + 1];
            const float4 w10 = Wg[(size_t)i * 32 + 2];
            const float4 w11 = Wg[(size_t)i * 32 + 3];
            const size_t obase = (size_t)i * BATCH + b0;
            #pragma unroll
            for (int bb = 0; bb < 8; bb++) {
                const int b = bbase + bb;
                const float4 xa = xs4[b * 16 + ii * 2];
                const float4 xb = xs4[b * 16 + ii * 2 + 1];
                float u0 = dot4(w00, xa) + dot4(w01, xb);
                float u1 = dot4(w10, xa) + dot4(w11, xb);
                uh2[(obase + b) * 80 + jd2] = __floats2half2_rn(u0, u1);
                acc0[bb] += u0;
                acc1[bb] += u1;
            }
        }
        #pragma unroll
        for (int bb = 0; bb < 8; bb++) {
            float* sb = &g_acc[(b0 + bbase + bb) * JD + jd2 * 2];
            atomicAdd(sb,     acc0[bb]);
            atomicAdd(sb + 1, acc1[bb]);
        }
    }
}

// -------- k_pass: barrier-free warp-gang routing (R14, unchanged) --------
// Warp = 3 b x 10 j on 30 lanes. Softmax over j via 4 ring shuffles.
// grid (36 i-chunks, 22 warp-quads), block 128. Zero __syncthreads.
__global__ __launch_bounds__(128, 6) void k_pass(int round) {
    const int wid  = threadIdx.x >> 5;
    const int lane = threadIdx.x & 31;
    const int gw   = blockIdx.y * GW + wid;      // 0..87
    const int bl10 = lane / 10;
    const int jj   = lane - bl10 * 10;           // j (garbage for lanes 30,31)
    const int b    = gw * 3 + bl10;
    const bool valid = (lane < 30) && (b < BATCH);
    const int bc   = (b < BATCH) ? b : (BATCH - 1);
    const int i0   = blockIdx.x * IT;

    const int base = bl10 * 10;
    const int s1 = base + (jj + 1) % 10;
    const int s2 = base + (jj + 2) % 10;
    const int s4 = base + (jj + 4) % 10;
    const int s8 = base + (jj + 8) % 10;

    // ---- vs[jj,:] = v0 (+ v1) — lane-local squash ----
    float vs[DN];
    {
        float tmp[DN]; float sq = 0.f;
        const float* a0 = g_acc + bc * JD + jj * DN;
        #pragma unroll
        for (int d = 0; d < DN; d++) { tmp[d] = 0.1f * a0[d]; sq += tmp[d]*tmp[d]; }
        float sc = (sq / (1.0f + sq)) * rsqrtf(sq + 1e-7f);
        #pragma unroll
        for (int d = 0; d < DN; d++) vs[d] = tmp[d] * sc;
        if (round == 2) {
            const float* a1 = g_acc + BJD + bc * JD + jj * DN;
            sq = 0.f;
            #pragma unroll
            for (int d = 0; d < DN; d++) { tmp[d] = a1[d]; sq += tmp[d]*tmp[d]; }
            sc = (sq / (1.0f + sq)) * rsqrtf(sq + 1e-7f);
            #pragma unroll
            for (int d = 0; d < DN; d++) vs[d] += tmp[d] * sc;
        }
    }

    const uint4* up = (const uint4*)(g_uhat
                    + (((size_t)i0 * BATCH + bc) * JN + jj) * DN);
    const size_t istep = (size_t)BATCH * JN * 2;   // uint4 per i

    float s[DN];
    #pragma unroll
    for (int d = 0; d < DN; d++) s[d] = 0.f;

    for (int t0 = 0; t0 < IT; t0 += 4) {
        uint4 lo[4], hi[4];
        float ev[4];
        #pragma unroll
        for (int k = 0; k < 4; k++) {
            const uint4* p = up + (size_t)(t0 + k) * istep;
            lo[k] = p[0];
            hi[k] = p[1];
            const __half2* h0 = (const __half2*)&lo[k];
            const __half2* h1 = (const __half2*)&hi[k];
            float a = 0.f;
            #pragma unroll
            for (int d2 = 0; d2 < 4; d2++) {
                float2 f0 = __half22float2(h0[d2]);
                a = fmaf(f0.x, vs[2*d2],     a);
                a = fmaf(f0.y, vs[2*d2 + 1], a);
                float2 f1 = __half22float2(h1[d2]);
                a = fmaf(f1.x, vs[8 + 2*d2], a);
                a = fmaf(f1.y, vs[9 + 2*d2], a);
            }
            ev[k] = fexp(a);
        }
        #pragma unroll
        for (int k = 0; k < 4; k++) {
            float e  = ev[k];
            float a1 = e  + __shfl_sync(0xffffffffu, e,  s1);
            float a2 = a1 + __shfl_sync(0xffffffffu, a1, s2);
            float a4 = a2 + __shfl_sync(0xffffffffu, a2, s4);
            float sum = a4 + __shfl_sync(0xffffffffu, a1, s8);
            float c = e * frcp(sum);
            const __half2* h0 = (const __half2*)&lo[k];
            const __half2* h1 = (const __half2*)&hi[k];
            #pragma unroll
            for (int d2 = 0; d2 < 4; d2++) {
                float2 f0 = __half22float2(h0[d2]);
                s[2*d2]     = fmaf(f0.x, c, s[2*d2]);
                s[2*d2 + 1] = fmaf(f0.y, c, s[2*d2 + 1]);
                float2 f1 = __half22float2(h1[d2]);
                s[8 + 2*d2] = fmaf(f1.x, c, s[8 + 2*d2]);
                s[9 + 2*d2] = fmaf(f1.y, c, s[9 + 2*d2]);
            }
        }
    }

    if (valid) {
        float* dst = g_part + (size_t)blockIdx.x * BJD + (size_t)b * JD + jj * DN;
        #pragma unroll
        for (int q = 0; q < 4; q++)
            ((float4*)dst)[q] = make_float4(s[4*q], s[4*q+1], s[4*q+2], s[4*q+3]);
    }
}

// -------- k_reduce: s1 = sum of NP partial slices (float4) ---------------
__global__ void k_reduce() {
    const int idx = blockIdx.x * 256 + threadIdx.x;   // < BJD/4
    const float4* p4 = (const float4*)g_part;
    float4 s = make_float4(0.f, 0.f, 0.f, 0.f);
    #pragma unroll 4
    for (int p = 0; p < NP; p++) {
        float4 v = p4[(size_t)p * (BJD / 4) + idx];
        s.x += v.x; s.y += v.y; s.z += v.z; s.w += v.w;
    }
    ((float4*)g_acc)[BJD / 4 + idx] = s;
}

// -------- k_final: out = squash(sum of partials), float4 -----------------
__global__ __launch_bounds__(256) void k_final(float* __restrict__ out) {
    const int idx = blockIdx.x * 256 + threadIdx.x;   // < BJD/4
    const float4* p4 = (const float4*)g_part;
    float4 v = make_float4(0.f, 0.f, 0.f, 0.f);
    #pragma unroll 4
    for (int p = 0; p < NP; p++) {
        float4 t = p4[(size_t)p * (BJD / 4) + idx];
        v.x += t.x; v.y += t.y; v.z += t.z; v.w += t.w;
    }
    float sq = v.x*v.x + v.y*v.y + v.z*v.z + v.w*v.w;
    sq += __shfl_xor_sync(0xffffffff, sq, 1);
    sq += __shfl_xor_sync(0xffffffff, sq, 2);
    float sc = (sq / (1.0f + sq)) * rsqrtf(sq + 1e-7f);
    v.x *= sc; v.y *= sc; v.z *= sc; v.w *= sc;
    ((float4*)out)[idx] = v;
}

// -------- launch --------------------------------------------------------
extern "C" void kernel_launch(void* const* d_in, const int* in_sizes, int n_in,
                              void* d_out, int out_size) {
    const float* x = (const float*)d_in[0];   // [256,1152,8]
    const float* W = (const float*)d_in[1];   // [10,1152,16,8]
    float* out = (float*)d_out;               // [256,10,16]

    void* acc_ptr = nullptr;
    cudaGetSymbolAddress(&acc_ptr, g_acc);
    cudaMemsetAsync(acc_ptr, 0, BJD * sizeof(float));   // s0 only

    k_uhat<<<dim3(ICAPS / 8, BATCH / 64), 320>>>(x, W);
    k_pass<<<dim3(NP, 22), 128>>>(1);
    k_reduce<<<BJD / 4 / 256, 256>>>();
    k_pass<<<dim3(NP, 22), 128>>>(2);
    k_final<<<BJD / 4 / 256, 256>>>(out);
}

// round 17
// speedup vs baseline: 1.4549x; 1.4549x over previous
#include <cuda_runtime.h>
#include <cuda_fp16.h>
#include <math.h>

#define BATCH   256
#define JN      10
#define ICAPS   1152
#define DN      16
#define JD      160          // JN*DN
#define BJD     (BATCH*JD)   // 40960
#define IT      32           // i per pass warp
#define NP      (ICAPS/IT)   // 36 partial slices
#define GW      4            // warps per pass CTA

// -------- scratch ------------------------------------------------------
// u_hat layout: [i][b][j][d] halves (32B per (i,b,j) entry; i outermost)
__device__ __align__(1024) __half g_uhat[(size_t)ICAPS * BATCH * JD]; // ~94.4MB
__device__ float g_acc[2 * BJD];                 // [0]=s0raw, [1]=s1
__device__ float g_part[(size_t)NP * BJD];       // ~5.9 MB

// -------- f32x2 helpers (k_uhat) ----------------------------------------
typedef unsigned long long u64t;
__device__ __forceinline__ u64t pack2(float x, float y) {
    u64t r; asm("mov.b64 %0, {%1, %2};" : "=l"(r) : "f"(x), "f"(y)); return r;
}
__device__ __forceinline__ void unpack2(u64t v, float& x, float& y) {
    asm("mov.b64 {%0, %1}, %2;" : "=f"(x), "=f"(y) : "l"(v));
}
__device__ __forceinline__ u64t fma2(u64t a, u64t b, u64t c) {
    u64t d; asm("fma.rn.f32x2 %0, %1, %2, %3;" : "=l"(d) : "l"(a), "l"(b), "l"(c));
    return d;
}
__device__ __forceinline__ u64t addf2(u64t a, u64t b) {
    u64t d; asm("add.rn.f32x2 %0, %1, %2;" : "=l"(d) : "l"(a), "l"(b)); return d;
}

// -------- MUFU-free exp / reciprocal (FMA+ALU pipes) ---------------------
__device__ __forceinline__ float fexp(float a) {
    float t = a * 1.44269504f;
    float m = t + 12582912.0f;
    int  ki = __float_as_int(m) - 0x4B400000;
    float f = t - (m - 12582912.0f);
    float p =             9.61812910e-3f;
    p = fmaf(p, f, 5.55041087e-2f);
    p = fmaf(p, f, 2.40226507e-1f);
    p = fmaf(p, f, 6.93147181e-1f);
    p = fmaf(p, f, 1.0f);
    return __int_as_float(__float_as_int(p) + (ki << 23));
}
__device__ __forceinline__ float frcp(float x) {
    float r = __int_as_float(0x7EF311C3 - __float_as_int(x));
    r = r * fmaf(-x, r, 2.0f);
    r = r * fmaf(-x, r, 2.0f);
    return r;
}

// -------- K1: u_hat = W @ x (fp16 [i][b][jd]), W-hoisted f32x2 -----------
// grid (72, 4), 320 threads: t%80 = jd2 (j*8+dp), t/80 = seg (16 b each).
// ii outer: W loaded+packed ONCE per ii (was twice); accs cover 8 b-pairs.
__global__ __launch_bounds__(320, 2) void k_uhat(const float* __restrict__ x,
                                                 const float* __restrict__ W) {
    __shared__ __align__(16) float xs[16 * 4 * 32 * 4];   // 32 KB interleaved x
    const int i0 = blockIdx.x * 16;
    const int b0 = blockIdx.y * 64;
    const int t  = threadIdx.x;

    const float4* xg = (const float4*)x;   // [256][1152][8] -> 2304 f4 per b
    for (int f = t; f < 2048; f += 320) {
        int b = f >> 5, q = f & 31;            // q = ii*2 + qe
        float4 v = xg[(size_t)(b0 + b) * 2304 + (size_t)i0 * 2 + q];
        int ii = q >> 1, qe = q & 1;
        int b2 = b >> 1, bl = b & 1;
        float* p = xs + (ii * 128 + qe * 64 + b2) * 4 + bl;
        p[0] = v.x; p[2] = v.y; p[128] = v.z; p[130] = v.w;
    }
    __syncthreads();

    const int jd2 = t % 80;          // j*8 + dp  (d0 = 2*dp)
    const int seg = t / 80;
    const int j   = jd2 >> 3, dp = jd2 & 7;
    const float4* Wg = (const float4*)W + (size_t)j * 36864 + dp * 4;
    __half2* uh2 = (__half2*)g_uhat;
    const ulonglong2* xq2base = (const ulonglong2*)xs;

    u64t s0a[8] = {0,0,0,0,0,0,0,0};
    u64t s1a[8] = {0,0,0,0,0,0,0,0};
    for (int ii = 0; ii < 16; ii++) {
        const int i = i0 + ii;
        const float4 w00 = Wg[(size_t)i * 32];
        const float4 w01 = Wg[(size_t)i * 32 + 1];
        const float4 w10 = Wg[(size_t)i * 32 + 2];
        const float4 w11 = Wg[(size_t)i * 32 + 3];
        u64t wd0[8], wd1[8];
        wd0[0]=pack2(w00.x,w00.x); wd0[1]=pack2(w00.y,w00.y);
        wd0[2]=pack2(w00.z,w00.z); wd0[3]=pack2(w00.w,w00.w);
        wd0[4]=pack2(w01.x,w01.x); wd0[5]=pack2(w01.y,w01.y);
        wd0[6]=pack2(w01.z,w01.z); wd0[7]=pack2(w01.w,w01.w);
        wd1[0]=pack2(w10.x,w10.x); wd1[1]=pack2(w10.y,w10.y);
        wd1[2]=pack2(w10.z,w10.z); wd1[3]=pack2(w10.w,w10.w);
        wd1[4]=pack2(w11.x,w11.x); wd1[5]=pack2(w11.y,w11.y);
        wd1[6]=pack2(w11.z,w11.z); wd1[7]=pack2(w11.w,w11.w);
        const ulonglong2* xq2 = xq2base + ii * 128;
        const size_t ibase = (size_t)i * BATCH;
        #pragma unroll
        for (int g = 0; g < 8; g++) {        // 8 b-pairs: b2 = seg*8 + g
            const int b2 = seg * 8 + g;
            u64t a0 = 0, a1 = 0;
            #pragma unroll
            for (int e2 = 0; e2 < 4; e2++) {
                ulonglong2 xv = xq2[e2 * 32 + b2];
                a0 = fma2(wd0[2*e2],   xv.x, a0);
                a0 = fma2(wd0[2*e2+1], xv.y, a0);
                a1 = fma2(wd1[2*e2],   xv.x, a1);
                a1 = fma2(wd1[2*e2+1], xv.y, a1);
            }
            float u00,u01,u10,u11;
            unpack2(a0, u00, u01);   // d0   : b_even, b_odd
            unpack2(a1, u10, u11);   // d0+1 : b_even, b_odd
            const int bg = b0 + 2*b2;
            uh2[(ibase + bg)     * 80 + jd2] = __floats2half2_rn(u00, u10);
            uh2[(ibase + bg + 1) * 80 + jd2] = __floats2half2_rn(u01, u11);
            s0a[g] = addf2(s0a[g], a0);
            s1a[g] = addf2(s1a[g], a1);
        }
    }
    #pragma unroll
    for (int g = 0; g < 8; g++) {
        float p0,p1,q0,q1;
        unpack2(s0a[g], p0, p1);
        unpack2(s1a[g], q0, q1);
        const int bg = b0 + 2*(seg * 8 + g);
        float* sb = &g_acc[bg * JD + jd2 * 2];
        atomicAdd(sb,           p0);
        atomicAdd(sb + 1,       q0);
        atomicAdd(sb + JD,      p1);
        atomicAdd(sb + JD + 1,  q1);
    }
}

// -------- k_pass: barrier-free warp-gang routing (R14, unchanged) --------
// Warp = 3 b x 10 j on 30 lanes. Softmax over j via 4 ring shuffles.
// grid (36 i-chunks, 22 warp-quads), block 128. Zero __syncthreads.
__global__ __launch_bounds__(128, 6) void k_pass(int round) {
    const int wid  = threadIdx.x >> 5;
    const int lane = threadIdx.x & 31;
    const int gw   = blockIdx.y * GW + wid;      // 0..87
    const int bl10 = lane / 10;
    const int jj   = lane - bl10 * 10;           // j (garbage for lanes 30,31)
    const int b    = gw * 3 + bl10;
    const bool valid = (lane < 30) && (b < BATCH);
    const int bc   = (b < BATCH) ? b : (BATCH - 1);
    const int i0   = blockIdx.x * IT;

    const int base = bl10 * 10;
    const int s1 = base + (jj + 1) % 10;
    const int s2 = base + (jj + 2) % 10;
    const int s4 = base + (jj + 4) % 10;
    const int s8 = base + (jj + 8) % 10;

    // ---- vs[jj,:] = v0 (+ v1) — lane-local squash ----
    float vs[DN];
    {
        float tmp[DN]; float sq = 0.f;
        const float* a0 = g_acc + bc * JD + jj * DN;
        #pragma unroll
        for (int d = 0; d < DN; d++) { tmp[d] = 0.1f * a0[d]; sq += tmp[d]*tmp[d]; }
        float sc = (sq / (1.0f + sq)) * rsqrtf(sq + 1e-7f);
        #pragma unroll
        for (int d = 0; d < DN; d++) vs[d] = tmp[d] * sc;
        if (round == 2) {
            const float* a1 = g_acc + BJD + bc * JD + jj * DN;
            sq = 0.f;
            #pragma unroll
            for (int d = 0; d < DN; d++) { tmp[d] = a1[d]; sq += tmp[d]*tmp[d]; }
            sc = (sq / (1.0f + sq)) * rsqrtf(sq + 1e-7f);
            #pragma unroll
            for (int d = 0; d < DN; d++) vs[d] += tmp[d] * sc;
        }
    }

    const uint4* up = (const uint4*)(g_uhat
                    + (((size_t)i0 * BATCH + bc) * JN + jj) * DN);
    const size_t istep = (size_t)BATCH * JN * 2;   // uint4 per i

    float s[DN];
    #pragma unroll
    for (int d = 0; d < DN; d++) s[d] = 0.f;

    for (int t0 = 0; t0 < IT; t0 += 4) {
        uint4 lo[4], hi[4];
        float ev[4];
        #pragma unroll
        for (int k = 0; k < 4; k++) {
            const uint4* p = up + (size_t)(t0 + k) * istep;
            lo[k] = p[0];
            hi[k] = p[1];
            const __half2* h0 = (const __half2*)&lo[k];
            const __half2* h1 = (const __half2*)&hi[k];
            float a = 0.f;
            #pragma unroll
            for (int d2 = 0; d2 < 4; d2++) {
                float2 f0 = __half22float2(h0[d2]);
                a = fmaf(f0.x, vs[2*d2],     a);
                a = fmaf(f0.y, vs[2*d2 + 1], a);
                float2 f1 = __half22float2(h1[d2]);
                a = fmaf(f1.x, vs[8 + 2*d2], a);
                a = fmaf(f1.y, vs[9 + 2*d2], a);
            }
            ev[k] = fexp(a);
        }
        #pragma unroll
        for (int k = 0; k < 4; k++) {
            float e  = ev[k];
            float a1 = e  + __shfl_sync(0xffffffffu, e,  s1);
            float a2 = a1 + __shfl_sync(0xffffffffu, a1, s2);
            float a4 = a2 + __shfl_sync(0xffffffffu, a2, s4);
            float sum = a4 + __shfl_sync(0xffffffffu, a1, s8);
            float c = e * frcp(sum);
            const __half2* h0 = (const __half2*)&lo[k];
            const __half2* h1 = (const __half2*)&hi[k];
            #pragma unroll
            for (int d2 = 0; d2 < 4; d2++) {
                float2 f0 = __half22float2(h0[d2]);
                s[2*d2]     = fmaf(f0.x, c, s[2*d2]);
                s[2*d2 + 1] = fmaf(f0.y, c, s[2*d2 + 1]);
                float2 f1 = __half22float2(h1[d2]);
                s[8 + 2*d2] = fmaf(f1.x, c, s[8 + 2*d2]);
                s[9 + 2*d2] = fmaf(f1.y, c, s[9 + 2*d2]);
            }
        }
    }

    if (valid) {
        float* dst = g_part + (size_t)blockIdx.x * BJD + (size_t)b * JD + jj * DN;
        #pragma unroll
        for (int q = 0; q < 4; q++)
            ((float4*)dst)[q] = make_float4(s[4*q], s[4*q+1], s[4*q+2], s[4*q+3]);
    }
}

// -------- k_reduce: s1 = sum of NP partial slices (float4) ---------------
__global__ void k_reduce() {
    const int idx = blockIdx.x * 256 + threadIdx.x;   // < BJD/4
    const float4* p4 = (const float4*)g_part;
    float4 s = make_float4(0.f, 0.f, 0.f, 0.f);
    #pragma unroll 4
    for (int p = 0; p < NP; p++) {
        float4 v = p4[(size_t)p * (BJD / 4) + idx];
        s.x += v.x; s.y += v.y; s.z += v.z; s.w += v.w;
    }
    ((float4*)g_acc)[BJD / 4 + idx] = s;
}

// -------- k_final: out = squash(sum of partials), float4 -----------------
__global__ __launch_bounds__(256) void k_final(float* __restrict__ out) {
    const int idx = blockIdx.x * 256 + threadIdx.x;   // < BJD/4
    const float4* p4 = (const float4*)g_part;
    float4 v = make_float4(0.f, 0.f, 0.f, 0.f);
    #pragma unroll 4
    for (int p = 0; p < NP; p++) {
        float4 t = p4[(size_t)p * (BJD / 4) + idx];
        v.x += t.x; v.y += t.y; v.z += t.z; v.w += t.w;
    }
    float sq = v.x*v.x + v.y*v.y + v.z*v.z + v.w*v.w;
    sq += __shfl_xor_sync(0xffffffff, sq, 1);
    sq += __shfl_xor_sync(0xffffffff, sq, 2);
    float sc = (sq / (1.0f + sq)) * rsqrtf(sq + 1e-7f);
    v.x *= sc; v.y *= sc; v.z *= sc; v.w *= sc;
    ((float4*)out)[idx] = v;
}

// -------- launch --------------------------------------------------------
extern "C" void kernel_launch(void* const* d_in, const int* in_sizes, int n_in,
                              void* d_out, int out_size) {
    const float* x = (const float*)d_in[0];   // [256,1152,8]
    const float* W = (const float*)d_in[1];   // [10,1152,16,8]
    float* out = (float*)d_out;               // [256,10,16]

    void* acc_ptr = nullptr;
    cudaGetSymbolAddress(&acc_ptr, g_acc);
    cudaMemsetAsync(acc_ptr, 0, BJD * sizeof(float));   // s0 only

    k_uhat<<<dim3(ICAPS / 16, BATCH / 64), 320>>>(x, W);
    k_pass<<<dim3(NP, 22), 128>>>(1);
    k_reduce<<<BJD / 4 / 256, 256>>>();
    k_pass<<<dim3(NP, 22), 128>>>(2);
    k_final<<<BJD / 4 / 256, 256>>>(out);
}